// round 11
// baseline (speedup 1.0000x reference)
#include <cuda_runtime.h>

#define Nn 384
#define Dm 256
#define MARGIN 0.2f
#define ANCH 3
#define NBLK (Nn / ANCH)   // 128
#define NTHR 384
#define NWARP 12
#define JB 4

typedef unsigned long long u64;

__device__ float    g_psum[NBLK];
__device__ int      g_pcnt[NBLK];
__device__ unsigned g_flag;      // zero-init; last block resets to 0 each run

__device__ __forceinline__ u64 ffma2(u64 a, u64 b, u64 c) {
    u64 d;
    asm("fma.rn.f32x2 %0, %1, %2, %3;" : "=l"(d) : "l"(a), "l"(b), "l"(c));
    return d;
}
__device__ __forceinline__ float hadd2(u64 p) {
    float lo, hi;
    asm("mov.b64 {%0, %1}, %2;" : "=f"(lo), "=f"(hi) : "l"(p));
    return lo + hi;
}

__global__ void __launch_bounds__(NTHR, 1)
k_fused(const float* __restrict__ e, const int* __restrict__ lab,
        float* __restrict__ out) {
    __shared__ ulonglong2 ea[ANCH * 64];  // raw anchor rows (packed f32x2 pairs)
    __shared__ float  Drow[ANCH][Nn];     // raw dots from phase 2
    __shared__ float  sssq[Nn];           // raw squared norms per j
    __shared__ int    slab[Nn];
    __shared__ float  pd3[ANCH][Nn];      // compacted positive distances per anchor
    __shared__ int    wcnt3[ANCH][NWARP];
    __shared__ float  rsum[NWARP];
    __shared__ int    rcnt[NWARP];
    __shared__ int    s_last;

    const int t = threadIdx.x, w = t >> 5, lane = t & 31;
    const int a0 = blockIdx.x * ANCH;

    if (t < Nn) slab[t] = lab[t];
    {
        const ulonglong2* src = (const ulonglong2*)(e + a0 * Dm);
        if (t < ANCH * 64) ea[t] = src[t];
    }
    __syncthreads();

    // ---- Phase 2: 8 lanes per j, 4 j's per warp, pipelined LDG, packed FMA ----
    const int jj = lane >> 3;            // which j within the group of 4
    const int kk = lane & 7;             // which k-slice (8x16B per lane)

    ulonglong2 v[8];
    {
        const ulonglong2* __restrict__ row = (const ulonglong2*)(e + (w * JB + jj) * Dm);
        #pragma unroll
        for (int c = 0; c < 8; c++) v[c] = row[kk + 8 * c];
    }

    #pragma unroll 1
    for (int jb = w * JB; jb < Nn; jb += NWARP * JB) {   // 8 iterations
        // prefetch next tile (wraps to row block 0 harmlessly on last iter)
        const int jbn = (jb + NWARP * JB < Nn) ? (jb + NWARP * JB) : 0;
        const ulonglong2* __restrict__ rown = (const ulonglong2*)(e + (jbn + jj) * Dm);
        ulonglong2 nv[8];
        #pragma unroll
        for (int c = 0; c < 8; c++) nv[c] = rown[kk + 8 * c];

        u64 qp = 0ull, s0 = 0ull, s1 = 0ull, s2 = 0ull;
        #pragma unroll
        for (int c = 0; c < 8; c++) {
            const int f = kk + 8 * c;
            ulonglong2 b0 = ea[0 * 64 + f];
            ulonglong2 b1 = ea[1 * 64 + f];
            ulonglong2 b2 = ea[2 * 64 + f];
            ulonglong2 vv = v[c];
            qp = ffma2(vv.x, vv.x, qp); qp = ffma2(vv.y, vv.y, qp);
            s0 = ffma2(b0.x, vv.x, s0); s0 = ffma2(b0.y, vv.y, s0);
            s1 = ffma2(b1.x, vv.x, s1); s1 = ffma2(b1.y, vv.y, s1);
            s2 = ffma2(b2.x, vv.x, s2); s2 = ffma2(b2.y, vv.y, s2);
        }
        float q  = hadd2(qp);
        float c0 = hadd2(s0);
        float c1 = hadd2(s1);
        float c2 = hadd2(s2);
        // reduce within 8-lane groups: 3 butterfly steps, 4 j's at once
        #pragma unroll
        for (int o = 1; o < 8; o <<= 1) {
            q  += __shfl_xor_sync(0xffffffffu, q,  o);
            c0 += __shfl_xor_sync(0xffffffffu, c0, o);
            c1 += __shfl_xor_sync(0xffffffffu, c1, o);
            c2 += __shfl_xor_sync(0xffffffffu, c2, o);
        }
        if (kk == 0) {
            const int j = jb + jj;
            sssq[j]    = q;
            Drow[0][j] = c0;
            Drow[1][j] = c1;
            Drow[2][j] = c2;
        }
        #pragma unroll
        for (int c = 0; c < 8; c++) v[c] = nv[c];
    }
    __syncthreads();

    // ---- Epilogue (registers) + single compaction pass for all 3 anchors ----
    float dn[ANCH];
    {
        float sj = rsqrtf(fmaxf(sssq[t], 1e-24f));
        #pragma unroll
        for (int aa = 0; aa < ANCH; aa++) {
            float sa = rsqrtf(fmaxf(sssq[a0 + aa], 1e-24f));
            float d2 = 2.0f - 2.0f * Drow[aa][t] * sa * sj;
            d2 = fmaxf(d2, 0.0f);
            dn[aa] = (d2 > 0.0f) ? sqrtf(d2) : 0.0f;
        }
    }

    const int myl = slab[t];
    int  la[ANCH];
    bool isp[ANCH];
    unsigned m[ANCH];
    #pragma unroll
    for (int aa = 0; aa < ANCH; aa++) {
        la[aa]  = slab[a0 + aa];
        isp[aa] = (myl == la[aa]) && (t != a0 + aa);
        m[aa]   = __ballot_sync(0xffffffffu, isp[aa]);
        if (lane == 0) wcnt3[aa][w] = __popc(m[aa]);
    }
    __syncthreads();

    int np[ANCH];
    #pragma unroll
    for (int aa = 0; aa < ANCH; aa++) {
        int off = 0, tot = 0;
        #pragma unroll
        for (int i = 0; i < NWARP; i++) {
            int c = wcnt3[aa][i];
            if (i < w) off += c;
            tot += c;
        }
        np[aa] = tot;
        if (isp[aa]) pd3[aa][off + __popc(m[aa] & ((1u << lane) - 1u))] = dn[aa];
    }
    __syncthreads();

    // ---- Scan: 3 anchors interleaved for ILP ----
    float lsum = 0.0f;
    int   lcnt = 0;
    {
        bool neg[ANCH];
        #pragma unroll
        for (int aa = 0; aa < ANCH; aa++) neg[aa] = (myl != la[aa]);
        int maxnp = np[0];
        if (np[1] > maxnp) maxnp = np[1];
        if (np[2] > maxnp) maxnp = np[2];
        for (int i = 0; i < maxnp; i++) {
            #pragma unroll
            for (int aa = 0; aa < ANCH; aa++) {
                if (neg[aa] && i < np[aa]) {
                    float tm = dn[aa] - pd3[aa][i];
                    // semihard & loss>0  <=>  0 < tm < MARGIN (tm==MARGIN adds 0)
                    if (tm > 0.0f && tm < MARGIN) { lsum += (MARGIN - tm); lcnt++; }
                }
            }
        }
    }

    // ---- Block reduction (fixed order, deterministic) ----
    #pragma unroll
    for (int o = 16; o > 0; o >>= 1) {
        lsum += __shfl_xor_sync(0xffffffffu, lsum, o);
        lcnt += __shfl_xor_sync(0xffffffffu, lcnt, o);
    }
    if (lane == 0) { rsum[w] = lsum; rcnt[w] = lcnt; }
    __syncthreads();
    if (t == 0) {
        float s = 0.0f; int c = 0;
        #pragma unroll
        for (int i = 0; i < NWARP; i++) { s += rsum[i]; c += rcnt[i]; }
        g_psum[blockIdx.x] = s;
        g_pcnt[blockIdx.x] = c;
        __threadfence();
        unsigned old = atomicAdd(&g_flag, 1u);
        s_last = (old == NBLK - 1) ? 1 : 0;
    }
    __syncthreads();

    // ---- Last block folds the 128 partials (deterministic order) ----
    if (s_last) {
        float s2 = (t < NBLK) ? g_psum[t] : 0.0f;
        int   c2 = (t < NBLK) ? g_pcnt[t] : 0;
        #pragma unroll
        for (int o = 16; o > 0; o >>= 1) {
            s2 += __shfl_xor_sync(0xffffffffu, s2, o);
            c2 += __shfl_xor_sync(0xffffffffu, c2, o);
        }
        if (lane == 0 && w < 4) { rsum[w] = s2; rcnt[w] = c2; }
        __syncthreads();
        if (t == 0) {
            float ts = rsum[0] + rsum[1] + rsum[2] + rsum[3];
            int   tc = rcnt[0] + rcnt[1] + rcnt[2] + rcnt[3];
            out[0] = (tc > 0) ? (ts / (float)tc) : 0.0f;
            g_flag = 0;   // reset for next graph replay
        }
    }
}

extern "C" void kernel_launch(void* const* d_in, const int* in_sizes, int n_in,
                              void* d_out, int out_size) {
    const float* e   = (const float*)d_in[0];
    const int*   lab = (const int*)d_in[1];
    k_fused<<<NBLK, NTHR>>>(e, lab, (float*)d_out);
}